// round 16
// baseline (speedup 1.0000x reference)
#include <cuda_runtime.h>
#include <cuda_bf16.h>
#include <cstdint>

// ─── Problem constants ────────────────────────────────────────────────
#define NROWS 8192       // 1024 clusters * 8
#define DIM   128
#define TM    128
#define TN    128
#define NMT   64                  // 64*65/2 = 2080 triangle tiles
#define NCTAS 130                 // 130 * 16 = 2080; all co-resident (1 CTA/SM)
#define TILES_PER_CTA 16

#define A_BYTES (TM * 256)
#define B_BYTES (TN * 256)
#define SMEM_REQ (2 * A_BYTES + 2 * B_BYTES)   // 128 KB: A + B double-buffered

__device__ __align__(16) __nv_bfloat16 g_ebf[NROWS * DIM];
__device__ float g_sqnorm[NROWS];
__device__ unsigned g_posu[NROWS];   // bits of squared hardest-positive (atomicMax)
__device__ unsigned g_negu[NROWS];   // bits of squared hardest-negative (atomicMin)
__device__ float g_partial[32];      // per-CTA partial sums (final kernel)
__device__ unsigned g_sync;          // hmma grid barrier  (reset by final kernel)
__device__ unsigned g_cnt;           // final election     (reset by final kernel)

// ─── PTX helpers (generic-target-safe) ────────────────────────────────
__device__ __forceinline__ uint32_t smem_u32(const void* p) {
    uint32_t a;
    asm("{ .reg .u64 t; cvta.to.shared.u64 t, %1; cvt.u32.u64 %0, t; }" : "=r"(a) : "l"(p));
    return a;
}
__device__ __forceinline__ void cp16(uint32_t dst, const void* src) {
    asm volatile("cp.async.cg.shared.global [%0], [%1], 16;" :: "r"(dst), "l"(src));
}
__device__ __forceinline__ void cp_commit() {
    asm volatile("cp.async.commit_group;" ::: "memory");
}
template <int N> __device__ __forceinline__ void cp_wait() {
    asm volatile("cp.async.wait_group %0;" :: "n"(N) : "memory");
}
#define LDSM_X4(r0, r1, r2, r3, addr) \
    asm volatile("ldmatrix.sync.aligned.m8n8.x4.shared.b16 {%0,%1,%2,%3}, [%4];" \
                 : "=r"(r0), "=r"(r1), "=r"(r2), "=r"(r3) : "r"(addr))
#define MMA16816(c, a, b0, b1) \
    asm volatile("mma.sync.aligned.m16n8k16.row.col.f32.bf16.bf16.f32 " \
                 "{%0,%1,%2,%3},{%4,%5,%6,%7},{%8,%9},{%0,%1,%2,%3};" \
                 : "+f"((c)[0]), "+f"((c)[1]), "+f"((c)[2]), "+f"((c)[3]) \
                 : "r"((a)[0]), "r"((a)[1]), "r"((a)[2]), "r"((a)[3]), "r"(b0), "r"(b1))

// ─── Inlined convert prologue (noinline: shields hmma's regalloc) ────
// CTA cid < 128 converts rows [cid*64, cid*64+64): 4 threads/row, 8 float4 each.
__device__ __noinline__ void convert_part(const float* __restrict__ E, int cid, int tid) {
    if (cid >= 128) return;
    int row = cid * 64 + (tid >> 2);
    int part = tid & 3;
    const float4* src = reinterpret_cast<const float4*>(E + (size_t)row * DIM + part * 32);
    uint32_t packed[16];
    float s = 0.f;
#pragma unroll
    for (int q = 0; q < 8; q++) {
        float4 v = src[q];
        __nv_bfloat16 bx = __float2bfloat16_rn(v.x), by = __float2bfloat16_rn(v.y);
        __nv_bfloat16 bz = __float2bfloat16_rn(v.z), bw = __float2bfloat16_rn(v.w);
        float fx = __bfloat162float(bx), fy = __bfloat162float(by);
        float fz = __bfloat162float(bz), fw = __bfloat162float(bw);
        s += fx * fx + fy * fy + fz * fz + fw * fw;
        packed[q * 2]     = ((uint32_t)__bfloat16_as_ushort(by) << 16) | __bfloat16_as_ushort(bx);
        packed[q * 2 + 1] = ((uint32_t)__bfloat16_as_ushort(bw) << 16) | __bfloat16_as_ushort(bz);
    }
    uint4* dst = reinterpret_cast<uint4*>(g_ebf + (size_t)row * DIM + part * 32);
#pragma unroll
    for (int q = 0; q < 4; q++)
        dst[q] = make_uint4(packed[4*q], packed[4*q+1], packed[4*q+2], packed[4*q+3]);
    s += __shfl_xor_sync(0xFFFFFFFFu, s, 1);
    s += __shfl_xor_sync(0xFFFFFFFFu, s, 2);
    if (part == 0) g_sqnorm[row] = s;
    if (tid < 64) {
        g_posu[cid * 64 + tid] = 0u;
        g_negu[cid * 64 + tid] = 0x7F800000u;
    }
}

// ─── Kernel 1: convert prologue + grid barrier + R12 hmma main loop ──
extern __shared__ char dsm[];

__global__ __launch_bounds__(256, 1) void hmma_kernel(const float* __restrict__ E) {
    __shared__ float s_norm[2][TN];
    __shared__ float s_p[4][TM];
    __shared__ float s_n[4][TM];

    const uint32_t as_u32[2] = { smem_u32(dsm), smem_u32(dsm + A_BYTES) };
    const uint32_t bs_u32[2] = { smem_u32(dsm + 2 * A_BYTES),
                                 smem_u32(dsm + 2 * A_BYTES + B_BYTES) };
    const uint32_t nrm_u32[2] = { smem_u32(s_norm[0]), smem_u32(s_norm[1]) };

    const int tid  = threadIdx.x;
    const int wid  = tid >> 5;
    const int lane = tid & 31;
    const int warp_m = wid >> 2;      // 0..1
    const int warp_n = wid & 3;       // 0..3

    // ── Phase 0: convert slice + software grid barrier (all CTAs resident) ──
    convert_part(E, blockIdx.x, tid);
    __threadfence();
    __syncthreads();
    if (tid == 0) {
        atomicAdd(&g_sync, 1u);
        volatile unsigned* p = &g_sync;
        while (*p < NCTAS) { }
    }
    __syncthreads();
    __threadfence();

    // ── Decode starting tile (mt, nt) of this CTA's 16-tile chunk ──
    int s0 = blockIdx.x * TILES_PER_CTA;
    int mt = 0, base = 0;
    while (base + (NMT - mt) <= s0) { base += NMT - mt; mt++; }
    int nt = mt + (s0 - base);

    // ── Loaders ──
    auto issue_a = [&](int m, int ab) {
        const char* src = (const char*)g_ebf + (size_t)m * TM * 256;
        uint32_t dst = as_u32[ab];
#pragma unroll
        for (int q = 0; q < 8; q++) {
            int idx = tid + q * 256;
            int r = idx >> 4, c = idx & 15;
            cp16(dst + r * 256 + ((c ^ (r & 7)) << 4), src + (size_t)r * 256 + c * 16);
        }
    };
    auto issue_b = [&](int n, int bb) {
        int jb = n * TN;
        const char* src = (const char*)g_ebf + (size_t)jb * 256;
        uint32_t dst = bs_u32[bb];
#pragma unroll
        for (int q = 0; q < 8; q++) {
            int idx = tid + q * 256;
            int r = idx >> 4, c = idx & 15;
            cp16(dst + r * 256 + ((c ^ (r & 7)) << 4), src + (size_t)r * 256 + c * 16);
        }
        if (tid < 32)
            cp16(nrm_u32[bb] + tid * 16, (const char*)(g_sqnorm + jb) + tid * 16);
    };

    int abuf = 0;
    issue_a(mt, 0);
    issue_b(nt, 0);
    cp_commit();

    // ── Per-thread row metadata ──
    float ni[4][2];
    int   ci[4][2];
    auto load_rowmeta = [&](int m) {
#pragma unroll
        for (int mi = 0; mi < 4; mi++)
#pragma unroll
            for (int h = 0; h < 2; h++) {
                int gi = m * TM + warp_m * 64 + mi * 16 + (lane >> 2) + h * 8;
                ni[mi][h] = g_sqnorm[gi];
                ci[mi][h] = gi >> 3;
            }
    };
    load_rowmeta(mt);

    float pm[4][2], nm[4][2];
#pragma unroll
    for (int mi = 0; mi < 4; mi++)
#pragma unroll
        for (int h = 0; h < 2; h++) { pm[mi][h] = 0.f; nm[mi][h] = 3.0e38f; }

    // Row flush: merge this CTA's partials for block m into global atomics.
    auto flush_rows = [&](int m) {
        __syncthreads();
#pragma unroll
        for (int mi = 0; mi < 4; mi++)
#pragma unroll
            for (int h = 0; h < 2; h++) {
                float p = pm[mi][h], n = nm[mi][h];
                p = fmaxf(p, __shfl_xor_sync(0xFFFFFFFFu, p, 1));
                p = fmaxf(p, __shfl_xor_sync(0xFFFFFFFFu, p, 2));
                n = fminf(n, __shfl_xor_sync(0xFFFFFFFFu, n, 1));
                n = fminf(n, __shfl_xor_sync(0xFFFFFFFFu, n, 2));
                if ((lane & 3) == 0) {
                    int r = warp_m * 64 + mi * 16 + (lane >> 2) + h * 8;
                    s_p[warp_n][r] = p;
                    s_n[warp_n][r] = n;
                }
            }
        __syncthreads();
        if (tid < TM) {
            float p = fmaxf(fmaxf(s_p[0][tid], s_p[1][tid]), fmaxf(s_p[2][tid], s_p[3][tid]));
            float n = fminf(fminf(s_n[0][tid], s_n[1][tid]), fminf(s_n[2][tid], s_n[3][tid]));
            atomicMax(&g_posu[m * TM + tid], __float_as_uint(p));
            atomicMin(&g_negu[m * TM + tid], __float_as_uint(n));
        }
#pragma unroll
        for (int mi = 0; mi < 4; mi++)
#pragma unroll
            for (int h = 0; h < 2; h++) { pm[mi][h] = 0.f; nm[mi][h] = 3.0e38f; }
        __syncthreads();
    };

    // ── ldmatrix address offsets ──
    uint32_t aRow[4], aSwz[4];
#pragma unroll
    for (int mi = 0; mi < 4; mi++) {
        int r = warp_m * 64 + mi * 16 + (lane & 15);
        aRow[mi] = r * 256;
        aSwz[mi] = r & 7;
    }
    uint32_t bRow[2], bSwz[2];
#pragma unroll
    for (int nb2 = 0; nb2 < 2; nb2++) {
        int r = warp_n * 32 + nb2 * 16 + ((lane >> 4) << 3) + (lane & 7);
        bRow[nb2] = r * 256;
        bSwz[nb2] = r & 7;
    }
    const uint32_t aChunkHi = lane >> 4;
    const uint32_t bChunkHi = (lane >> 3) & 1;

    // ── Main loop over this CTA's 16 triangle tiles ──
    int m_done = mt;
    for (int t = 0; t < TILES_PER_CTA; t++) {
        m_done = mt;
        int mt2 = mt, nt2 = nt + 1;
        bool mchange = false;
        if (nt2 == NMT) { mt2 = mt + 1; nt2 = mt2; mchange = true; }
        if (t + 1 < TILES_PER_CTA) {
            if (mchange) issue_a(mt2, abuf ^ 1);
            issue_b(nt2, (t + 1) & 1);
            cp_commit();
            cp_wait<1>();
        } else {
            cp_wait<0>();
        }
        __syncthreads();

        // ── GEMM 128x128x128 ──
        float acc[4][4][4];
#pragma unroll
        for (int mi = 0; mi < 4; mi++)
#pragma unroll
            for (int nb = 0; nb < 4; nb++)
#pragma unroll
                for (int e = 0; e < 4; e++) acc[mi][nb][e] = 0.f;

        const uint32_t ab = as_u32[abuf];
        const uint32_t bb = bs_u32[t & 1];
#pragma unroll
        for (int k = 0; k < 8; k++) {
            uint32_t a[4][4];
#pragma unroll
            for (int mi = 0; mi < 4; mi++) {
                uint32_t ad = ab + aRow[mi] + (((2 * k + aChunkHi) ^ aSwz[mi]) << 4);
                LDSM_X4(a[mi][0], a[mi][1], a[mi][2], a[mi][3], ad);
            }
            uint32_t b[2][4];
#pragma unroll
            for (int nb2 = 0; nb2 < 2; nb2++) {
                uint32_t bd = bb + bRow[nb2] + (((2 * k + bChunkHi) ^ bSwz[nb2]) << 4);
                LDSM_X4(b[nb2][0], b[nb2][1], b[nb2][2], b[nb2][3], bd);
            }
#pragma unroll
            for (int mi = 0; mi < 4; mi++) {
                MMA16816(acc[mi][0], a[mi], b[0][0], b[0][1]);
                MMA16816(acc[mi][1], a[mi], b[0][2], b[0][3]);
                MMA16816(acc[mi][2], a[mi], b[1][0], b[1][1]);
                MMA16816(acc[mi][3], a[mi], b[1][2], b[1][3]);
            }
        }

        // ── Fused mining epilogue: row partials + column partials ──
        const int jt = nt * TN;
        const bool do_cols = (nt != mt);
        float cpx[4][2], cnx[4][2];
#pragma unroll
        for (int nb = 0; nb < 4; nb++) {
            cpx[nb][0] = cpx[nb][1] = 0.f;
            cnx[nb][0] = cnx[nb][1] = 3.0e38f;
        }
#pragma unroll
        for (int nb = 0; nb < 4; nb++) {
            int cl = warp_n * 32 + nb * 8 + ((lane & 3) << 1);
            float nj0 = s_norm[t & 1][cl], nj1 = s_norm[t & 1][cl + 1];
            int cj = (jt + cl) >> 3;
#pragma unroll
            for (int mi = 0; mi < 4; mi++)
#pragma unroll
                for (int h = 0; h < 2; h++) {
                    float bs = ni[mi][h];
                    float s0v = fmaxf(fmaf(-2.0f, acc[mi][nb][h * 2 + 0], bs + nj0), 0.0f);
                    float s1v = fmaxf(fmaf(-2.0f, acc[mi][nb][h * 2 + 1], bs + nj1), 0.0f);
                    if (cj == ci[mi][h]) {
                        pm[mi][h] = fmaxf(pm[mi][h], fmaxf(s0v, s1v));
                        cpx[nb][0] = fmaxf(cpx[nb][0], s0v);
                        cpx[nb][1] = fmaxf(cpx[nb][1], s1v);
                    } else {
                        nm[mi][h] = fminf(nm[mi][h], fminf(s0v, s1v));
                        cnx[nb][0] = fminf(cnx[nb][0], s0v);
                        cnx[nb][1] = fminf(cnx[nb][1], s1v);
                    }
                }
        }
        if (do_cols) {
#pragma unroll
            for (int nb = 0; nb < 4; nb++)
#pragma unroll
                for (int c2 = 0; c2 < 2; c2++) {
                    float p = cpx[nb][c2], n = cnx[nb][c2];
#pragma unroll
                    for (int d = 4; d <= 16; d <<= 1) {
                        p = fmaxf(p, __shfl_xor_sync(0xFFFFFFFFu, p, d));
                        n = fminf(n, __shfl_xor_sync(0xFFFFFFFFu, n, d));
                    }
                    if (lane < 4) {
                        int j = jt + warp_n * 32 + nb * 8 + lane * 2 + c2;
                        atomicMax(&g_posu[j], __float_as_uint(p));
                        atomicMin(&g_negu[j], __float_as_uint(n));
                    }
                }
        }

        // advance; flush rows on mt change
        if (t + 1 < TILES_PER_CTA && mchange) {
            flush_rows(mt);
            abuf ^= 1;
            load_rowmeta(mt2);
        } else {
            __syncthreads();
        }
        mt = mt2;
        nt = nt2;
    }
    flush_rows(m_done);   // flush block of the LAST PROCESSED tile
}

// ─── Kernel 2: parallel final reduction (32 CTAs, deterministic) ─────
__global__ void final_kernel(float* __restrict__ out) {
    __shared__ float red[256];
    __shared__ int s_last;
    int tid = threadIdx.x;
    int i = blockIdx.x * 256 + tid;             // one row per thread
    float ap = sqrtf(__uint_as_float(g_posu[i]));
    float an = sqrtf(__uint_as_float(g_negu[i]));
    float s = fmaxf(ap - an + 1.0f, 0.0f);
    red[tid] = s;
    __syncthreads();
    for (int st = 128; st > 0; st >>= 1) {
        if (tid < st) red[tid] += red[tid + st];
        __syncthreads();
    }
    if (tid == 0) {
        g_partial[blockIdx.x] = red[0];
        __threadfence();
        unsigned v = atomicAdd(&g_cnt, 1u);
        s_last = (v == 31u) ? 1 : 0;
    }
    __syncthreads();
    if (s_last && tid == 0) {
        __threadfence();
        float sum = 0.f;
#pragma unroll
        for (int b = 0; b < 32; b++) sum += g_partial[b];   // fixed order
        out[0] = sum / (float)NROWS;
        g_sync = 0u;                  // reset barriers for next replay
        g_cnt  = 0u;
    }
}

extern "C" void kernel_launch(void* const* d_in, const int* in_sizes, int n_in,
                              void* d_out, int out_size) {
    const float* E = (const float*)d_in[0];
    float* out = (float*)d_out;

    cudaFuncSetAttribute(hmma_kernel, cudaFuncAttributeMaxDynamicSharedMemorySize, SMEM_REQ);

    hmma_kernel<<<NCTAS, 256, SMEM_REQ>>>(E);
    final_kernel<<<32, 256>>>(out);
}

// round 17
// speedup vs baseline: 1.1127x; 1.1127x over previous
#include <cuda_runtime.h>
#include <cuda_bf16.h>
#include <cstdint>

// ─── Problem constants ────────────────────────────────────────────────
#define NROWS 8192       // 1024 clusters * 8
#define DIM   128
#define TM    128
#define TN    128
#define NMT   64                  // 64*65/2 = 2080 triangle tiles
#define NCTAS 148                 // 8 x 15 tiles + 140 x 14 = 2080 (full chip)

#define A_BYTES (TM * 256)
#define B_BYTES (TN * 256)
#define SMEM_REQ (2 * A_BYTES + 2 * B_BYTES)   // 128 KB: A + B double-buffered

__device__ __align__(16) __nv_bfloat16 g_ebf[NROWS * DIM];
__device__ float g_sqnorm[NROWS];
__device__ unsigned g_posu[NROWS];   // bits of squared hardest-positive (atomicMax)
__device__ unsigned g_negu[NROWS];   // bits of squared hardest-negative (atomicMin)
__device__ float g_partial[32];      // per-CTA partial sums (final kernel)
__device__ unsigned g_cnt;           // final-kernel election (reset by convert)

// ─── PTX helpers (generic-target-safe) ────────────────────────────────
__device__ __forceinline__ uint32_t smem_u32(const void* p) {
    uint32_t a;
    asm("{ .reg .u64 t; cvta.to.shared.u64 t, %1; cvt.u32.u64 %0, t; }" : "=r"(a) : "l"(p));
    return a;
}
__device__ __forceinline__ void cp16(uint32_t dst, const void* src) {
    asm volatile("cp.async.cg.shared.global [%0], [%1], 16;" :: "r"(dst), "l"(src));
}
__device__ __forceinline__ void cp_commit() {
    asm volatile("cp.async.commit_group;" ::: "memory");
}
template <int N> __device__ __forceinline__ void cp_wait() {
    asm volatile("cp.async.wait_group %0;" :: "n"(N) : "memory");
}
#define LDSM_X4(r0, r1, r2, r3, addr) \
    asm volatile("ldmatrix.sync.aligned.m8n8.x4.shared.b16 {%0,%1,%2,%3}, [%4];" \
                 : "=r"(r0), "=r"(r1), "=r"(r2), "=r"(r3) : "r"(addr))
#define MMA16816(c, a, b0, b1) \
    asm volatile("mma.sync.aligned.m16n8k16.row.col.f32.bf16.bf16.f32 " \
                 "{%0,%1,%2,%3},{%4,%5,%6,%7},{%8,%9},{%0,%1,%2,%3};" \
                 : "+f"((c)[0]), "+f"((c)[1]), "+f"((c)[2]), "+f"((c)[3]) \
                 : "r"((a)[0]), "r"((a)[1]), "r"((a)[2]), "r"((a)[3]), "r"(b0), "r"(b1))

// ─── Kernel 1: fp32 -> bf16 convert + norms + init globals ───────────
// 512 CTAs x 256 threads: 16 threads/row, 2 float4 each (best measured).
__global__ void convert_kernel(const float* __restrict__ E) {
    int gid = blockIdx.x * 256 + threadIdx.x;   // 131072 threads: 16 per row
    if (gid == 0) g_cnt = 0u;
    if (gid < NROWS) { g_posu[gid] = 0u; g_negu[gid] = 0x7F800000u; }
    int row = gid >> 4, hseg = gid & 15;        // 8 elems per thread (2 x float4)
    float s = 0.f;
    uint2 pk[2];
#pragma unroll
    for (int q = 0; q < 2; q++) {
        float4 v = *reinterpret_cast<const float4*>(E + (size_t)row * DIM + hseg * 8 + q * 4);
        __nv_bfloat16 bx = __float2bfloat16_rn(v.x), by = __float2bfloat16_rn(v.y);
        __nv_bfloat16 bz = __float2bfloat16_rn(v.z), bw = __float2bfloat16_rn(v.w);
        float fx = __bfloat162float(bx), fy = __bfloat162float(by);
        float fz = __bfloat162float(bz), fw = __bfloat162float(bw);
        s += fx * fx + fy * fy + fz * fz + fw * fw;
        pk[q].x = ((uint32_t)__bfloat16_as_ushort(by) << 16) | __bfloat16_as_ushort(bx);
        pk[q].y = ((uint32_t)__bfloat16_as_ushort(bw) << 16) | __bfloat16_as_ushort(bz);
    }
    *reinterpret_cast<uint4*>(g_ebf + (size_t)row * DIM + hseg * 8) =
        make_uint4(pk[0].x, pk[0].y, pk[1].x, pk[1].y);
#pragma unroll
    for (int d = 8; d > 0; d >>= 1) s += __shfl_xor_sync(0xFFFFFFFFu, s, d);
    if (hseg == 0) g_sqnorm[row] = s;
}

// ─── Kernel 2: upper-triangle HMMA GEMM + dual (row+col) mining ──────
// Loop body = R12/R15 (frozen, 128-reg). Only the chunk schedule changes:
// 148 CTAs, 15/14-tile chunks -> critical path 16 -> 15, full-chip.
extern __shared__ char dsm[];

__global__ __launch_bounds__(256, 1) void hmma_kernel() {
    __shared__ float s_norm[2][TN];
    __shared__ float s_p[4][TM];
    __shared__ float s_n[4][TM];

    const uint32_t as_u32[2] = { smem_u32(dsm), smem_u32(dsm + A_BYTES) };
    const uint32_t bs_u32[2] = { smem_u32(dsm + 2 * A_BYTES),
                                 smem_u32(dsm + 2 * A_BYTES + B_BYTES) };
    const uint32_t nrm_u32[2] = { smem_u32(s_norm[0]), smem_u32(s_norm[1]) };

    const int tid  = threadIdx.x;
    const int wid  = tid >> 5;
    const int lane = tid & 31;
    const int warp_m = wid >> 2;      // 0..1
    const int warp_n = wid & 3;       // 0..3

    // ── This CTA's chunk: 8 CTAs x 15 tiles, then 140 x 14 ──
    const int cnt = (blockIdx.x < 8) ? 15 : 14;
    int s0 = (blockIdx.x < 8) ? blockIdx.x * 15 : 120 + (blockIdx.x - 8) * 14;
    int mt = 0, base = 0;
    while (base + (NMT - mt) <= s0) { base += NMT - mt; mt++; }
    int nt = mt + (s0 - base);

    // ── Loaders ──
    auto issue_a = [&](int m, int ab) {
        const char* src = (const char*)g_ebf + (size_t)m * TM * 256;
        uint32_t dst = as_u32[ab];
#pragma unroll
        for (int q = 0; q < 8; q++) {
            int idx = tid + q * 256;
            int r = idx >> 4, c = idx & 15;
            cp16(dst + r * 256 + ((c ^ (r & 7)) << 4), src + (size_t)r * 256 + c * 16);
        }
    };
    auto issue_b = [&](int n, int bb) {
        int jb = n * TN;
        const char* src = (const char*)g_ebf + (size_t)jb * 256;
        uint32_t dst = bs_u32[bb];
#pragma unroll
        for (int q = 0; q < 8; q++) {
            int idx = tid + q * 256;
            int r = idx >> 4, c = idx & 15;
            cp16(dst + r * 256 + ((c ^ (r & 7)) << 4), src + (size_t)r * 256 + c * 16);
        }
        if (tid < 32)
            cp16(nrm_u32[bb] + tid * 16, (const char*)(g_sqnorm + jb) + tid * 16);
    };

    int abuf = 0;
    issue_a(mt, 0);
    issue_b(nt, 0);
    cp_commit();

    // ── Per-thread row metadata ──
    float ni[4][2];
    int   ci[4][2];
    auto load_rowmeta = [&](int m) {
#pragma unroll
        for (int mi = 0; mi < 4; mi++)
#pragma unroll
            for (int h = 0; h < 2; h++) {
                int gi = m * TM + warp_m * 64 + mi * 16 + (lane >> 2) + h * 8;
                ni[mi][h] = g_sqnorm[gi];
                ci[mi][h] = gi >> 3;
            }
    };
    load_rowmeta(mt);

    float pm[4][2], nm[4][2];
#pragma unroll
    for (int mi = 0; mi < 4; mi++)
#pragma unroll
        for (int h = 0; h < 2; h++) { pm[mi][h] = 0.f; nm[mi][h] = 3.0e38f; }

    // Row flush: merge this CTA's partials for block m into global atomics.
    auto flush_rows = [&](int m) {
        __syncthreads();
#pragma unroll
        for (int mi = 0; mi < 4; mi++)
#pragma unroll
            for (int h = 0; h < 2; h++) {
                float p = pm[mi][h], n = nm[mi][h];
                p = fmaxf(p, __shfl_xor_sync(0xFFFFFFFFu, p, 1));
                p = fmaxf(p, __shfl_xor_sync(0xFFFFFFFFu, p, 2));
                n = fminf(n, __shfl_xor_sync(0xFFFFFFFFu, n, 1));
                n = fminf(n, __shfl_xor_sync(0xFFFFFFFFu, n, 2));
                if ((lane & 3) == 0) {
                    int r = warp_m * 64 + mi * 16 + (lane >> 2) + h * 8;
                    s_p[warp_n][r] = p;
                    s_n[warp_n][r] = n;
                }
            }
        __syncthreads();
        if (tid < TM) {
            float p = fmaxf(fmaxf(s_p[0][tid], s_p[1][tid]), fmaxf(s_p[2][tid], s_p[3][tid]));
            float n = fminf(fminf(s_n[0][tid], s_n[1][tid]), fminf(s_n[2][tid], s_n[3][tid]));
            atomicMax(&g_posu[m * TM + tid], __float_as_uint(p));
            atomicMin(&g_negu[m * TM + tid], __float_as_uint(n));
        }
#pragma unroll
        for (int mi = 0; mi < 4; mi++)
#pragma unroll
            for (int h = 0; h < 2; h++) { pm[mi][h] = 0.f; nm[mi][h] = 3.0e38f; }
        __syncthreads();
    };

    // ── ldmatrix address offsets ──
    uint32_t aRow[4], aSwz[4];
#pragma unroll
    for (int mi = 0; mi < 4; mi++) {
        int r = warp_m * 64 + mi * 16 + (lane & 15);
        aRow[mi] = r * 256;
        aSwz[mi] = r & 7;
    }
    uint32_t bRow[2], bSwz[2];
#pragma unroll
    for (int nb2 = 0; nb2 < 2; nb2++) {
        int r = warp_n * 32 + nb2 * 16 + ((lane >> 4) << 3) + (lane & 7);
        bRow[nb2] = r * 256;
        bSwz[nb2] = r & 7;
    }
    const uint32_t aChunkHi = lane >> 4;
    const uint32_t bChunkHi = (lane >> 3) & 1;

    // ── Main loop over this CTA's tiles ──
    int m_done = mt;
    for (int t = 0; t < cnt; t++) {
        m_done = mt;
        int mt2 = mt, nt2 = nt + 1;
        bool mchange = false;
        if (nt2 == NMT) { mt2 = mt + 1; nt2 = mt2; mchange = true; }
        if (t + 1 < cnt) {
            if (mchange) issue_a(mt2, abuf ^ 1);
            issue_b(nt2, (t + 1) & 1);
            cp_commit();
            cp_wait<1>();
        } else {
            cp_wait<0>();
        }
        __syncthreads();

        // ── GEMM 128x128x128 ──
        float acc[4][4][4];
#pragma unroll
        for (int mi = 0; mi < 4; mi++)
#pragma unroll
            for (int nb = 0; nb < 4; nb++)
#pragma unroll
                for (int e = 0; e < 4; e++) acc[mi][nb][e] = 0.f;

        const uint32_t ab = as_u32[abuf];
        const uint32_t bb = bs_u32[t & 1];
#pragma unroll
        for (int k = 0; k < 8; k++) {
            uint32_t a[4][4];
#pragma unroll
            for (int mi = 0; mi < 4; mi++) {
                uint32_t ad = ab + aRow[mi] + (((2 * k + aChunkHi) ^ aSwz[mi]) << 4);
                LDSM_X4(a[mi][0], a[mi][1], a[mi][2], a[mi][3], ad);
            }
            uint32_t b[2][4];
#pragma unroll
            for (int nb2 = 0; nb2 < 2; nb2++) {
                uint32_t bd = bb + bRow[nb2] + (((2 * k + bChunkHi) ^ bSwz[nb2]) << 4);
                LDSM_X4(b[nb2][0], b[nb2][1], b[nb2][2], b[nb2][3], bd);
            }
#pragma unroll
            for (int mi = 0; mi < 4; mi++) {
                MMA16816(acc[mi][0], a[mi], b[0][0], b[0][1]);
                MMA16816(acc[mi][1], a[mi], b[0][2], b[0][3]);
                MMA16816(acc[mi][2], a[mi], b[1][0], b[1][1]);
                MMA16816(acc[mi][3], a[mi], b[1][2], b[1][3]);
            }
        }

        // ── Fused mining epilogue: row partials + column partials ──
        const int jt = nt * TN;
        const bool do_cols = (nt != mt);
        float cpx[4][2], cnx[4][2];
#pragma unroll
        for (int nb = 0; nb < 4; nb++) {
            cpx[nb][0] = cpx[nb][1] = 0.f;
            cnx[nb][0] = cnx[nb][1] = 3.0e38f;
        }
#pragma unroll
        for (int nb = 0; nb < 4; nb++) {
            int cl = warp_n * 32 + nb * 8 + ((lane & 3) << 1);
            float nj0 = s_norm[t & 1][cl], nj1 = s_norm[t & 1][cl + 1];
            int cj = (jt + cl) >> 3;
#pragma unroll
            for (int mi = 0; mi < 4; mi++)
#pragma unroll
                for (int h = 0; h < 2; h++) {
                    float bs = ni[mi][h];
                    float s0v = fmaxf(fmaf(-2.0f, acc[mi][nb][h * 2 + 0], bs + nj0), 0.0f);
                    float s1v = fmaxf(fmaf(-2.0f, acc[mi][nb][h * 2 + 1], bs + nj1), 0.0f);
                    if (cj == ci[mi][h]) {
                        pm[mi][h] = fmaxf(pm[mi][h], fmaxf(s0v, s1v));
                        cpx[nb][0] = fmaxf(cpx[nb][0], s0v);
                        cpx[nb][1] = fmaxf(cpx[nb][1], s1v);
                    } else {
                        nm[mi][h] = fminf(nm[mi][h], fminf(s0v, s1v));
                        cnx[nb][0] = fminf(cnx[nb][0], s0v);
                        cnx[nb][1] = fminf(cnx[nb][1], s1v);
                    }
                }
        }
        if (do_cols) {
#pragma unroll
            for (int nb = 0; nb < 4; nb++)
#pragma unroll
                for (int c2 = 0; c2 < 2; c2++) {
                    float p = cpx[nb][c2], n = cnx[nb][c2];
#pragma unroll
                    for (int d = 4; d <= 16; d <<= 1) {
                        p = fmaxf(p, __shfl_xor_sync(0xFFFFFFFFu, p, d));
                        n = fminf(n, __shfl_xor_sync(0xFFFFFFFFu, n, d));
                    }
                    if (lane < 4) {
                        int j = jt + warp_n * 32 + nb * 8 + lane * 2 + c2;
                        atomicMax(&g_posu[j], __float_as_uint(p));
                        atomicMin(&g_negu[j], __float_as_uint(n));
                    }
                }
        }

        // advance; flush rows on mt change
        if (t + 1 < cnt && mchange) {
            flush_rows(mt);
            abuf ^= 1;
            load_rowmeta(mt2);
        } else {
            __syncthreads();
        }
        mt = mt2;
        nt = nt2;
    }
    flush_rows(m_done);   // flush block of the LAST PROCESSED tile
}

// ─── Kernel 3: parallel final reduction (32 CTAs, deterministic) ─────
__global__ void final_kernel(float* __restrict__ out) {
    __shared__ float red[256];
    __shared__ int s_last;
    int tid = threadIdx.x;
    int i = blockIdx.x * 256 + tid;             // one row per thread
    float ap = sqrtf(__uint_as_float(g_posu[i]));
    float an = sqrtf(__uint_as_float(g_negu[i]));
    float s = fmaxf(ap - an + 1.0f, 0.0f);
    red[tid] = s;
    __syncthreads();
    for (int st = 128; st > 0; st >>= 1) {
        if (tid < st) red[tid] += red[tid + st];
        __syncthreads();
    }
    if (tid == 0) {
        g_partial[blockIdx.x] = red[0];
        __threadfence();
        unsigned v = atomicAdd(&g_cnt, 1u);
        s_last = (v == 31u) ? 1 : 0;
    }
    __syncthreads();
    if (s_last && tid == 0) {
        __threadfence();
        float sum = 0.f;
#pragma unroll
        for (int b = 0; b < 32; b++) sum += g_partial[b];   // fixed order
        out[0] = sum / (float)NROWS;
    }
}

extern "C" void kernel_launch(void* const* d_in, const int* in_sizes, int n_in,
                              void* d_out, int out_size) {
    const float* E = (const float*)d_in[0];
    float* out = (float*)d_out;

    cudaFuncSetAttribute(hmma_kernel, cudaFuncAttributeMaxDynamicSharedMemorySize, SMEM_REQ);

    convert_kernel<<<512, 256>>>(E);
    hmma_kernel<<<NCTAS, 256, SMEM_REQ>>>();
    final_kernel<<<32, 256>>>(out);
}